// round 2
// baseline (speedup 1.0000x reference)
#include <cuda_runtime.h>
#include <math.h>
#include <stdint.h>

#define Nn 128
#define Tt 256
#define Dd 1024
#define Hh 1024
#define G4 4096
#define Pp 196
#define KK 3072   // [x_t | h | attn]

// ---- device scratch (no allocation allowed) ----
__device__ float g_Wf[(size_t)KK * G4];   // permuted [Wx;Wh;Wattn], col j' = u*4+g
__device__ float g_bf[G4];                // permuted bias
__device__ float g_act[(size_t)Nn * KK];  // per-step activation rows [x_t | h | attn]
__device__ float g_c[Nn * Hh];            // cell state

__device__ __forceinline__ float2 ffma2(float2 a, float2 b, float2 c) {
    float2 d;
    asm("fma.rn.f32x2 %0, %1, %2, %3;"
        : "=l"(reinterpret_cast<unsigned long long&>(d))
        : "l"(reinterpret_cast<unsigned long long&>(a)),
          "l"(reinterpret_cast<unsigned long long&>(b)),
          "l"(reinterpret_cast<unsigned long long&>(c)));
    return d;
}

// ---- one-time: permute weights to gate-interleaved layout ----
__global__ __launch_bounds__(256) void permute_kernel(
    const float* __restrict__ Wx, const float* __restrict__ Wh,
    const float* __restrict__ Wa, const float* __restrict__ b) {
    size_t total = (size_t)KK * G4;
    size_t stride = (size_t)gridDim.x * blockDim.x;
    for (size_t idx = (size_t)blockIdx.x * blockDim.x + threadIdx.x; idx < total; idx += stride) {
        int k = (int)(idx >> 12);
        int j = (int)(idx & 4095);
        int src = (j & 3) * 1024 + (j >> 2);   // gate g, unit u -> g*1024+u
        float v;
        if (k < 1024)       v = Wx[(size_t)k * G4 + src];
        else if (k < 2048)  v = Wh[(size_t)(k - 1024) * G4 + src];
        else                v = Wa[(size_t)(k - 2048) * G4 + src];
        g_Wf[idx] = v;
        if (idx < G4) g_bf[idx] = b[src];
    }
}

// ---- h0 = c0 = mean_p A[n,u,:] ----
__global__ __launch_bounds__(256) void init_kernel(const float* __restrict__ A) {
    int n = blockIdx.x;
    for (int u = threadIdx.x; u < Hh; u += blockDim.x) {
        const float4* r = (const float4*)(A + ((size_t)n * Hh + u) * Pp);
        float s = 0.f;
#pragma unroll
        for (int i = 0; i < 49; i++) {
            float4 v = r[i];
            s += v.x + v.y + v.z + v.w;
        }
        float m = s * (1.f / 196.f);
        g_act[(size_t)n * KK + 1024 + u] = m;   // h0
        g_c[n * Hh + u] = m;                    // c0
    }
}

// ---- per-step attention: scores -> softmax -> weighted sum; also copies x_t ----
__global__ __launch_bounds__(256) void attn_kernel(
    const float* __restrict__ A, const float* __restrict__ x, int t) {
    int n = blockIdx.x;
    int tid = threadIdx.x;
    __shared__ __align__(16) float hsh[1024];
    __shared__ __align__(16) float w[200];
    __shared__ float red[256];

    float* actn = g_act + (size_t)n * KK;
    const float* xt = x + ((size_t)n * Tt + t) * Dd;
    for (int k = tid; k < 1024; k += 256) {
        actn[k] = xt[k];              // x_t slice of Act
        hsh[k] = actn[1024 + k];      // current h
    }
    __syncthreads();

    const float* An = A + (size_t)n * Hh * Pp;
    float myscore = 0.f;
    float s = -3.4e38f;
    if (tid < Pp) {
        float acc = 0.f;
        const float* ap = An + tid;
#pragma unroll 8
        for (int u = 0; u < 1024; u++) {
            acc += hsh[u] * ap[0];
            ap += Pp;
        }
        myscore = acc * 0.03125f;     // 1/sqrt(1024)
        s = myscore;
    }
    red[tid] = s;
    __syncthreads();
    for (int off = 128; off > 0; off >>= 1) {
        if (tid < off) red[tid] = fmaxf(red[tid], red[tid + off]);
        __syncthreads();
    }
    float mx = red[0];
    __syncthreads();
    float e = (tid < Pp) ? expf(myscore - mx) : 0.f;
    red[tid] = e;
    __syncthreads();
    for (int off = 128; off > 0; off >>= 1) {
        if (tid < off) red[tid] += red[tid + off];
        __syncthreads();
    }
    float inv = 1.f / red[0];
    if (tid < Pp) w[tid] = e * inv;
    __syncthreads();

    // attn[u] = sum_p A[n,u,p] * w[p]
    for (int u = tid; u < 1024; u += 256) {
        const float4* Ar = (const float4*)(An + (size_t)u * Pp);
        float acc = 0.f;
#pragma unroll
        for (int i = 0; i < 49; i++) {
            float4 av = Ar[i];
            float4 wv = *(const float4*)&w[4 * i];
            acc += av.x * wv.x + av.y * wv.y + av.z * wv.z + av.w * wv.w;
        }
        actn[2048 + u] = acc;
    }
}

// ---- per-step GEMM (128x4096, K=3072) + fused LSTM epilogue ----
// grid 128 (col tiles of 32), 256 threads, thread = 4 rows x 4 cols (one unit's gates)
__global__ __launch_bounds__(256) void gates_kernel(float* __restrict__ out, int t) {
    __shared__ __align__(16) float As[32][128];
    __shared__ __align__(16) float Bs[32][32];

    int tid = threadIdx.x;
    int j0 = blockIdx.x * 32;
    int tx = tid & 7;          // col group (4 cols = 1 unit)
    int ty = tid >> 3;         // row group (4 rows), 0..31

    int am = tid & 127;        // Act row to load
    int ah = (tid >> 7) * 16;  // k offset within tile
    int bk = tid >> 3;         // Wf row within tile
    int bc = (tid & 7) * 4;    // Wf col within tile

    float2 c2[4][2];
#pragma unroll
    for (int r = 0; r < 4; r++) { c2[r][0] = make_float2(0.f, 0.f); c2[r][1] = make_float2(0.f, 0.f); }

    const float* arow = g_act + (size_t)am * KK + ah;
    const float* bptr = g_Wf + (size_t)bk * G4 + j0 + bc;

    for (int kt = 0; kt < KK / 32; kt++) {
        int k0 = kt * 32;
        float4 ra[4];
#pragma unroll
        for (int i = 0; i < 4; i++) ra[i] = *(const float4*)(arow + k0 + 4 * i);
        float4 rb = *(const float4*)(bptr + (size_t)k0 * G4);
        __syncthreads();
#pragma unroll
        for (int i = 0; i < 4; i++) {
            As[ah + 4 * i + 0][am] = ra[i].x;
            As[ah + 4 * i + 1][am] = ra[i].y;
            As[ah + 4 * i + 2][am] = ra[i].z;
            As[ah + 4 * i + 3][am] = ra[i].w;
        }
        *(float4*)&Bs[bk][bc] = rb;
        __syncthreads();
#pragma unroll
        for (int k = 0; k < 32; k++) {
            float4 av = *(const float4*)&As[k][ty * 4];
            float4 bv = *(const float4*)&Bs[k][tx * 4];
            float2 b0 = make_float2(bv.x, bv.y);
            float2 b1 = make_float2(bv.z, bv.w);
            c2[0][0] = ffma2(make_float2(av.x, av.x), b0, c2[0][0]);
            c2[0][1] = ffma2(make_float2(av.x, av.x), b1, c2[0][1]);
            c2[1][0] = ffma2(make_float2(av.y, av.y), b0, c2[1][0]);
            c2[1][1] = ffma2(make_float2(av.y, av.y), b1, c2[1][1]);
            c2[2][0] = ffma2(make_float2(av.z, av.z), b0, c2[2][0]);
            c2[2][1] = ffma2(make_float2(av.z, av.z), b1, c2[2][1]);
            c2[3][0] = ffma2(make_float2(av.w, av.w), b0, c2[3][0]);
            c2[3][1] = ffma2(make_float2(av.w, av.w), b1, c2[3][1]);
        }
    }

    // epilogue: this thread owns unit u for rows ty*4..ty*4+3
    int u = (j0 >> 2) + tx;
    float4 bf4 = *(const float4*)&g_bf[j0 + tx * 4];
#pragma unroll
    for (int r = 0; r < 4; r++) {
        int m = ty * 4 + r;
        float ai = c2[r][0].x + bf4.x;
        float af = c2[r][0].y + bf4.y;
        float ao = c2[r][1].x + bf4.z;
        float ag = c2[r][1].y + bf4.w;
        float ig = 1.f / (1.f + expf(-ai));
        float fg = 1.f / (1.f + expf(-af));
        float og = 1.f / (1.f + expf(-ao));
        float gg = tanhf(ag);
        float cn = fg * g_c[m * Hh + u] + ig * gg;
        float hn = og * tanhf(cn);
        g_c[m * Hh + u] = cn;
        g_act[(size_t)m * KK + 1024 + u] = hn;
        out[((size_t)m * Tt + t) * Hh + u] = hn;
    }
}

extern "C" void kernel_launch(void* const* d_in, const int* in_sizes, int n_in,
                              void* d_out, int out_size) {
    const float* x  = (const float*)d_in[0];
    const float* A  = (const float*)d_in[1];
    const float* Wx = (const float*)d_in[2];
    const float* Wh = (const float*)d_in[3];
    const float* Wa = (const float*)d_in[4];
    const float* b  = (const float*)d_in[5];
    float* out = (float*)d_out;

    permute_kernel<<<2048, 256>>>(Wx, Wh, Wa, b);
    init_kernel<<<Nn, 256>>>(A);
    for (int t = 0; t < Tt; t++) {
        attn_kernel<<<Nn, 256>>>(A, x, t);
        gates_kernel<<<G4 / 32, 256>>>(out, t);
    }
}